// round 3
// baseline (speedup 1.0000x reference)
#include <cuda_runtime.h>
#include <math.h>

#define NTOK 2048      // b*t
#define CDIM 512       // input dim
#define DQ   2048      // query dim = 2*H*DH
#define NH   8
#define NKEY 256
#define DH   128
#define TK   32
#define NEG_INF (-3.402823466e38f)

// ---------------- scratch (device globals; no allocations allowed) ----------
__device__ float g_q[NTOK * DQ];            // 16 MB  [t][p][h][d] (flat = reshape order)
__device__ float g_dots[16 * NTOK * NKEY];  // 32 MB  [hp][t][n], hp = h*2+p
__device__ float g_sx[NTOK * 16 * TK];      // [t][h][p][k]  sorted desc
__device__ int   g_ix[NTOK * 16 * TK];
__device__ float g_w [NTOK * NH * TK];      // softmax weights
__device__ int   g_vi[NTOK * NH * TK];      // value row indices

// ---------------- 1) Q = X @ Wq^T  (M=2048,N=2048,K=512, fp32) --------------
__global__ __launch_bounds__(256) void sgemm_q(const float* __restrict__ X,
                                               const float* __restrict__ W) {
  __shared__ float As[16][128];   // transposed: As[k][m]
  __shared__ float Bs[16][64];    // transposed: Bs[k][n]
  const int m0 = blockIdx.y * 128;
  const int n0 = blockIdx.x * 64;
  const int tid = threadIdx.x;
  const int tm = tid >> 4;   // 0..15 -> 8 rows each
  const int tn = tid & 15;   // 0..15 -> 4 cols each
  const int ar = tid >> 2;   // 0..63
  const int ac = (tid & 3) * 4;

  float acc[8][4];
  #pragma unroll
  for (int i = 0; i < 8; i++) {
    #pragma unroll
    for (int j = 0; j < 4; j++) acc[i][j] = 0.0f;
  }

  for (int k0 = 0; k0 < CDIM; k0 += 16) {
    #pragma unroll
    for (int i = 0; i < 2; i++) {
      int r = ar + i * 64;
      float4 v = *(const float4*)(X + (size_t)(m0 + r) * CDIM + k0 + ac);
      As[ac + 0][r] = v.x; As[ac + 1][r] = v.y;
      As[ac + 2][r] = v.z; As[ac + 3][r] = v.w;
    }
    {
      float4 v = *(const float4*)(W + (size_t)(n0 + ar) * CDIM + k0 + ac);
      Bs[ac + 0][ar] = v.x; Bs[ac + 1][ar] = v.y;
      Bs[ac + 2][ar] = v.z; Bs[ac + 3][ar] = v.w;
    }
    __syncthreads();
    #pragma unroll
    for (int k = 0; k < 16; k++) {
      float4 b  = *(const float4*)&Bs[k][tn * 4];
      float4 a0 = *(const float4*)&As[k][tm * 8];
      float4 a1 = *(const float4*)&As[k][tm * 8 + 4];
      float av[8] = {a0.x, a0.y, a0.z, a0.w, a1.x, a1.y, a1.z, a1.w};
      float bv[4] = {b.x, b.y, b.z, b.w};
      #pragma unroll
      for (int i = 0; i < 8; i++) {
        #pragma unroll
        for (int j = 0; j < 4; j++) acc[i][j] = fmaf(av[i], bv[j], acc[i][j]);
      }
    }
    __syncthreads();
  }
  #pragma unroll
  for (int i = 0; i < 8; i++) {
    float4 v = make_float4(acc[i][0], acc[i][1], acc[i][2], acc[i][3]);
    *(float4*)(g_q + (size_t)(m0 + tm * 8 + i) * DQ + n0 + tn * 4) = v;
  }
}

// ---------------- 2) LayerNorm over each 128-group, in place ----------------
__global__ __launch_bounds__(256) void ln_kernel(const float* __restrict__ gamma,
                                                 const float* __restrict__ beta) {
  int g    = blockIdx.x * 8 + (threadIdx.x >> 5);   // 0..32767 (flat 128-groups)
  int lane = threadIdx.x & 31;
  float* base = g_q + (size_t)g * DH;
  float v[4];
  #pragma unroll
  for (int j = 0; j < 4; j++) v[j] = base[lane + j * 32];
  float s = v[0] + v[1] + v[2] + v[3];
  #pragma unroll
  for (int o = 16; o > 0; o >>= 1) s += __shfl_xor_sync(0xffffffffu, s, o);
  float mean = s * (1.0f / 128.0f);
  float d[4];
  #pragma unroll
  for (int j = 0; j < 4; j++) d[j] = v[j] - mean;
  float sq = d[0]*d[0] + d[1]*d[1] + d[2]*d[2] + d[3]*d[3];
  #pragma unroll
  for (int o = 16; o > 0; o >>= 1) sq += __shfl_xor_sync(0xffffffffu, sq, o);
  float rs = rsqrtf(sq * (1.0f / 128.0f) + 1e-5f);
  #pragma unroll
  for (int j = 0; j < 4; j++) {
    int c = lane + j * 32;
    base[c] = d[j] * rs * gamma[c] + beta[c];
  }
}

// ---------------- 3) dots[hp][t][n] = q[t,p,h,:] . keys[h,n,p,:] ------------
__global__ __launch_bounds__(256) void dots_kernel(const float* __restrict__ keys) {
  __shared__ float Qs[32][64];   // Qs[k][m]
  __shared__ float Ks[32][64];   // Ks[k][n]
  const int hp = blockIdx.z;
  const int h = hp >> 1, p = hp & 1;
  const int t0 = blockIdx.y * 64;
  const int n0 = blockIdx.x * 64;
  const int tid = threadIdx.x;
  const int tm = tid >> 4, tn = tid & 15;

  const float* qbase = g_q + p * 1024 + h * 128;                 // + t*2048 + d
  const float* kbase = keys + ((size_t)h * NKEY * 2 + p) * DH;   // + n*256 + d

  float acc[4][4];
  #pragma unroll
  for (int i = 0; i < 4; i++) {
    #pragma unroll
    for (int j = 0; j < 4; j++) acc[i][j] = 0.0f;
  }

  for (int kt = 0; kt < DH; kt += 32) {
    #pragma unroll
    for (int i = 0; i < 2; i++) {
      int idx = tid + i * 256;
      int r = idx >> 3, c4 = (idx & 7) * 4;
      float4 v = *(const float4*)(qbase + (size_t)(t0 + r) * DQ + kt + c4);
      Qs[c4 + 0][r] = v.x; Qs[c4 + 1][r] = v.y;
      Qs[c4 + 2][r] = v.z; Qs[c4 + 3][r] = v.w;
    }
    #pragma unroll
    for (int i = 0; i < 2; i++) {
      int idx = tid + i * 256;
      int r = idx >> 3, c4 = (idx & 7) * 4;
      float4 v = *(const float4*)(kbase + (size_t)(n0 + r) * 256 + kt + c4);
      Ks[c4 + 0][r] = v.x; Ks[c4 + 1][r] = v.y;
      Ks[c4 + 2][r] = v.z; Ks[c4 + 3][r] = v.w;
    }
    __syncthreads();
    #pragma unroll
    for (int k = 0; k < 32; k++) {
      float4 a = *(const float4*)&Qs[k][tm * 4];
      float4 b = *(const float4*)&Ks[k][tn * 4];
      float av[4] = {a.x, a.y, a.z, a.w};
      float bv[4] = {b.x, b.y, b.z, b.w};
      #pragma unroll
      for (int i = 0; i < 4; i++) {
        #pragma unroll
        for (int j = 0; j < 4; j++) acc[i][j] = fmaf(av[i], bv[j], acc[i][j]);
      }
    }
    __syncthreads();
  }
  #pragma unroll
  for (int i = 0; i < 4; i++) {
    float4 v = make_float4(acc[i][0], acc[i][1], acc[i][2], acc[i][3]);
    *(float4*)(g_dots + ((size_t)hp * NTOK + t0 + tm * 4 + i) * NKEY + n0 + tn * 4) = v;
  }
}

// ---------------- 4) top-32 of 256 per (t,h,p); sorted desc; ties -> low idx -
__global__ __launch_bounds__(256) void topk1_kernel() {
  int w    = (blockIdx.x * 256 + threadIdx.x) >> 5;  // 0..32767
  int lane = threadIdx.x & 31;
  int t  = w >> 4;
  int hp = w & 15;
  const float* row = g_dots + ((size_t)hp * NTOK + t) * NKEY;
  float v[8];
  #pragma unroll
  for (int j = 0; j < 8; j++) v[j] = row[j * 32 + lane];

  float selS = 0.0f; int selI = 0;
  for (int r = 0; r < TK; r++) {
    float bv = NEG_INF; int bi = 0x7fffffff;
    #pragma unroll
    for (int j = 0; j < 8; j++) {
      int idx = j * 32 + lane;
      bool better = (v[j] > bv) || (v[j] == bv && idx < bi);
      if (better) { bv = v[j]; bi = idx; }
    }
    #pragma unroll
    for (int o = 16; o > 0; o >>= 1) {
      float ov = __shfl_xor_sync(0xffffffffu, bv, o);
      int   oi = __shfl_xor_sync(0xffffffffu, bi, o);
      bool better = (ov > bv) || (ov == bv && oi < bi);
      if (better) { bv = ov; bi = oi; }
    }
    if (lane == r) { selS = bv; selI = bi; }
    #pragma unroll
    for (int j = 0; j < 8; j++)
      if (bi == j * 32 + lane) v[j] = NEG_INF;
  }
  int hh = hp >> 1, pp = hp & 1;
  size_t ob = (((size_t)t * NH + hh) * 2 + pp) * TK;
  g_sx[ob + lane] = selS;
  g_ix[ob + lane] = selI;
}

// ---- 5) cartesian combine top-32-of-1024 via 32-way sorted merge + softmax -
__global__ __launch_bounds__(256) void combine_kernel() {
  int w    = (blockIdx.x * 256 + threadIdx.x) >> 5;  // 0..16383
  int lane = threadIdx.x & 31;
  int t = w >> 3, h = w & 7;
  size_t bx = (((size_t)t * NH + h) * 2 + 0) * TK;
  float sx = g_sx[bx + lane];
  float sy = g_sx[bx + TK + lane];
  int  ixv = g_ix[bx + lane];
  int  iyv = g_ix[bx + TK + lane];

  int ptr = 0;                 // next unconsumed j in this lane's (sorted) row
  float selS = 0.0f; int selVI = 0;
  for (int r = 0; r < TK; r++) {
    float syv  = __shfl_sync(0xffffffffu, sy, ptr & 31);
    float cand = (ptr < TK) ? (sx + syv) : NEG_INF;
    float bv = cand; int bl = lane;
    #pragma unroll
    for (int o = 16; o > 0; o >>= 1) {
      float ov = __shfl_xor_sync(0xffffffffu, bv, o);
      int   ol = __shfl_xor_sync(0xffffffffu, bl, o);
      if ((ov > bv) || (ov == bv && ol < bl)) { bv = ov; bl = ol; }
    }
    // ties resolve to lower lane == lower flattened i*32+j, matching lax.top_k
    int jw  = __shfl_sync(0xffffffffu, ptr, bl);
    int ixw = __shfl_sync(0xffffffffu, ixv, bl);
    int iyw = __shfl_sync(0xffffffffu, iyv, jw & 31);
    if (lane == r) { selS = bv; selVI = ixw * NKEY + iyw; }
    if (lane == bl) ptr++;
  }
  float mx = __shfl_sync(0xffffffffu, selS, 0);   // sorted desc -> lane0 is max
  float e = expf(selS - mx);
  float sum = e;
  #pragma unroll
  for (int o = 16; o > 0; o >>= 1) sum += __shfl_xor_sync(0xffffffffu, sum, o);
  size_t ob = ((size_t)t * NH + h) * TK;
  g_w [ob + lane] = e / sum;
  g_vi[ob + lane] = selVI;
}

// ---------------- 6) out[t] = sum_{h,k} w * values[vi]  (gather) ------------
__global__ __launch_bounds__(128) void gather_kernel(const float* __restrict__ values,
                                                     float* __restrict__ out) {
  __shared__ float sw[NH * TK];
  __shared__ int   sv[NH * TK];
  int t = blockIdx.x;
  int tid = threadIdx.x;
  size_t base = (size_t)t * (NH * TK);
  sw[tid]       = g_w [base + tid];
  sv[tid]       = g_vi[base + tid];
  sw[tid + 128] = g_w [base + tid + 128];
  sv[tid + 128] = g_vi[base + tid + 128];
  __syncthreads();

  const float4* V = (const float4*)values;   // 128 float4 per 512-float row
  float4 acc = make_float4(0.f, 0.f, 0.f, 0.f);
  #pragma unroll 4
  for (int r = 0; r < NH * TK; r++) {
    float wv = sw[r];
    float4 x = V[(size_t)sv[r] * 128 + tid];
    acc.x = fmaf(wv, x.x, acc.x);
    acc.y = fmaf(wv, x.y, acc.y);
    acc.z = fmaf(wv, x.z, acc.z);
    acc.w = fmaf(wv, x.w, acc.w);
  }
  ((float4*)out)[(size_t)t * 128 + tid] = acc;
}

// ---------------- launch --------------------------------------------------
extern "C" void kernel_launch(void* const* d_in, const int* in_sizes, int n_in,
                              void* d_out, int out_size) {
  const float* x      = (const float*)d_in[0];  // (2,1024,512)
  const float* Wq     = (const float*)d_in[1];  // (2048,512)
  const float* keys   = (const float*)d_in[2];  // (8,256,2,128)
  const float* values = (const float*)d_in[3];  // (65536,512)
  const float* gamma  = (const float*)d_in[4];  // (128)
  const float* beta   = (const float*)d_in[5];  // (128)
  float* out = (float*)d_out;                   // (2,1024,512)

  sgemm_q    <<<dim3(32, 16), 256>>>(x, Wq);
  ln_kernel  <<<4096, 256>>>(gamma, beta);
  dots_kernel<<<dim3(4, 32, 16), 256>>>(keys);
  topk1_kernel<<<4096, 256>>>();
  combine_kernel<<<2048, 256>>>();
  gather_kernel<<<2048, 128>>>(values, out);
}

// round 4
// speedup vs baseline: 1.1855x; 1.1855x over previous
#include <cuda_runtime.h>
#include <math.h>

#define NTOK 2048      // b*t
#define CDIM 512       // input dim
#define DQ   2048      // query dim = 2*H*DH
#define NH   8
#define NKEY 256
#define DH   128
#define TK   32
#define NEG_INF (-3.402823466e38f)

// ---------------- scratch (device globals; no allocations allowed) ----------
__device__ float g_q[NTOK * DQ];            // 16 MB  [t][p][h][d]
__device__ float g_sx[NTOK * 16 * TK];      // [t][h][p][k]  sorted desc
__device__ int   g_ix[NTOK * 16 * TK];
__device__ float g_w [NTOK * NH * TK];      // softmax weights
__device__ int   g_vi[NTOK * NH * TK];      // value row indices

// ---------------- 1) Q = X @ Wq^T  (M=2048,N=2048,K=512, fp32) --------------
__global__ __launch_bounds__(256) void sgemm_q(const float* __restrict__ X,
                                               const float* __restrict__ W) {
  __shared__ float As[16][128];   // transposed: As[k][m]
  __shared__ float Bs[16][64];    // transposed: Bs[k][n]
  const int m0 = blockIdx.y * 128;
  const int n0 = blockIdx.x * 64;
  const int tid = threadIdx.x;
  const int tm = tid >> 4;
  const int tn = tid & 15;
  const int ar = tid >> 2;
  const int ac = (tid & 3) * 4;

  float acc[8][4];
  #pragma unroll
  for (int i = 0; i < 8; i++) {
    #pragma unroll
    for (int j = 0; j < 4; j++) acc[i][j] = 0.0f;
  }

  for (int k0 = 0; k0 < CDIM; k0 += 16) {
    #pragma unroll
    for (int i = 0; i < 2; i++) {
      int r = ar + i * 64;
      float4 v = *(const float4*)(X + (size_t)(m0 + r) * CDIM + k0 + ac);
      As[ac + 0][r] = v.x; As[ac + 1][r] = v.y;
      As[ac + 2][r] = v.z; As[ac + 3][r] = v.w;
    }
    {
      float4 v = *(const float4*)(W + (size_t)(n0 + ar) * CDIM + k0 + ac);
      Bs[ac + 0][ar] = v.x; Bs[ac + 1][ar] = v.y;
      Bs[ac + 2][ar] = v.z; Bs[ac + 3][ar] = v.w;
    }
    __syncthreads();
    #pragma unroll
    for (int k = 0; k < 16; k++) {
      float4 b  = *(const float4*)&Bs[k][tn * 4];
      float4 a0 = *(const float4*)&As[k][tm * 8];
      float4 a1 = *(const float4*)&As[k][tm * 8 + 4];
      float av[8] = {a0.x, a0.y, a0.z, a0.w, a1.x, a1.y, a1.z, a1.w};
      float bv[4] = {b.x, b.y, b.z, b.w};
      #pragma unroll
      for (int i = 0; i < 8; i++) {
        #pragma unroll
        for (int j = 0; j < 4; j++) acc[i][j] = fmaf(av[i], bv[j], acc[i][j]);
      }
    }
    __syncthreads();
  }
  #pragma unroll
  for (int i = 0; i < 8; i++) {
    float4 v = make_float4(acc[i][0], acc[i][1], acc[i][2], acc[i][3]);
    *(float4*)(g_q + (size_t)(m0 + tm * 8 + i) * DQ + n0 + tn * 4) = v;
  }
}

// ---------------- 2) LayerNorm over each 128-group, in place ----------------
__global__ __launch_bounds__(256) void ln_kernel(const float* __restrict__ gamma,
                                                 const float* __restrict__ beta) {
  int g    = blockIdx.x * 8 + (threadIdx.x >> 5);
  int lane = threadIdx.x & 31;
  float* base = g_q + (size_t)g * DH;
  float v[4];
  #pragma unroll
  for (int j = 0; j < 4; j++) v[j] = base[lane + j * 32];
  float s = v[0] + v[1] + v[2] + v[3];
  #pragma unroll
  for (int o = 16; o > 0; o >>= 1) s += __shfl_xor_sync(0xffffffffu, s, o);
  float mean = s * (1.0f / 128.0f);
  float d[4];
  #pragma unroll
  for (int j = 0; j < 4; j++) d[j] = v[j] - mean;
  float sq = d[0]*d[0] + d[1]*d[1] + d[2]*d[2] + d[3]*d[3];
  #pragma unroll
  for (int o = 16; o > 0; o >>= 1) sq += __shfl_xor_sync(0xffffffffu, sq, o);
  float rs = rsqrtf(sq * (1.0f / 128.0f) + 1e-5f);
  #pragma unroll
  for (int j = 0; j < 4; j++) {
    int c = lane + j * 32;
    base[c] = d[j] * rs * gamma[c] + beta[c];
  }
}

// ---------------- bitonic helpers on u64 keys (desc, exact tie-break) -------
__device__ __forceinline__ unsigned long long kmax(unsigned long long a,
                                                   unsigned long long b) {
  return a > b ? a : b;
}
__device__ __forceinline__ unsigned long long kmin(unsigned long long a,
                                                   unsigned long long b) {
  return a < b ? a : b;
}
// merge two descending sorted-32 (one elem/lane) -> top-32 of union, desc
__device__ __forceinline__ unsigned long long merge_top32(
    unsigned long long a, unsigned long long b, int lane) {
  unsigned long long br = __shfl_sync(0xffffffffu, b, 31 - lane);
  unsigned long long m = kmax(a, br);   // bitonic, contains top-32
  #pragma unroll
  for (int j = 16; j > 0; j >>= 1) {
    unsigned long long o = __shfl_xor_sync(0xffffffffu, m, j);
    m = ((lane & j) == 0) ? kmax(m, o) : kmin(m, o);
  }
  return m;
}

// ------- 3+4) fused: dots (per hp, 64 tokens/block) + bitonic top-32 --------
// Warp w owns tokens t0+8w..t0+8w+7; lane owns key columns rr*32+lane.
__global__ __launch_bounds__(256) void dots_topk_kernel(const float* __restrict__ keys) {
  __shared__ float Qs[32][65];    // Qs[k][m] padded: conflict-free
  __shared__ float Ks[32][257];   // Ks[k][n] padded: conflict-free
  const int hp = blockIdx.y;              // 0..15
  const int h = hp >> 1, p = hp & 1;
  const int t0 = blockIdx.x * 64;
  const int tid = threadIdx.x;
  const int lane = tid & 31;
  const int w = tid >> 5;                 // warp 0..7

  const float* qbase = g_q + p * 1024 + h * 128;            // + t*DQ + d
  const float* kbase = keys + ((size_t)h * 512 + p) * 128;  // + n*256 + d

  float acc[8][8];                        // [token i][rr]
  #pragma unroll
  for (int i = 0; i < 8; i++)
    #pragma unroll
    for (int rr = 0; rr < 8; rr++) acc[i][rr] = 0.0f;

  for (int kt = 0; kt < DH; kt += 32) {
    #pragma unroll
    for (int i = 0; i < 2; i++) {
      int idx = tid + i * 256;            // 0..511
      int m = idx >> 3, c4 = (idx & 7) * 4;
      float4 v = *(const float4*)(qbase + (size_t)(t0 + m) * DQ + kt + c4);
      Qs[c4 + 0][m] = v.x; Qs[c4 + 1][m] = v.y;
      Qs[c4 + 2][m] = v.z; Qs[c4 + 3][m] = v.w;
    }
    #pragma unroll
    for (int i = 0; i < 8; i++) {
      int idx = tid + i * 256;            // 0..2047
      int n = idx >> 3, c4 = (idx & 7) * 4;
      float4 v = *(const float4*)(kbase + (size_t)n * 256 + kt + c4);
      Ks[c4 + 0][n] = v.x; Ks[c4 + 1][n] = v.y;
      Ks[c4 + 2][n] = v.z; Ks[c4 + 3][n] = v.w;
    }
    __syncthreads();
    #pragma unroll 1
    for (int k = 0; k < 32; k++) {
      float qv[8], kv[8];
      #pragma unroll
      for (int i = 0; i < 8; i++) qv[i] = Qs[k][w * 8 + i];     // broadcast
      #pragma unroll
      for (int rr = 0; rr < 8; rr++) kv[rr] = Ks[k][rr * 32 + lane];
      #pragma unroll
      for (int i = 0; i < 8; i++)
        #pragma unroll
        for (int rr = 0; rr < 8; rr++)
          acc[i][rr] = fmaf(qv[i], kv[rr], acc[i][rr]);
    }
    __syncthreads();
  }

  // ---- per-token top-32 via bitonic sort + prune-merge tree ----
  #pragma unroll 1
  for (int i = 0; i < 8; i++) {
    int t = t0 + w * 8 + i;
    unsigned long long kk[8];
    #pragma unroll
    for (int rr = 0; rr < 8; rr++) {
      unsigned u = __float_as_uint(acc[0][rr]);          // token data in slot 0
      u = (u & 0x80000000u) ? ~u : (u | 0x80000000u);    // monotonic map
      int idx = rr * 32 + lane;
      kk[rr] = ((unsigned long long)u << 8) | (unsigned)(idx ^ 0xff);
    }
    // rotate acc so next token's data moves into slot 0 (no dynamic reg index)
    #pragma unroll
    for (int s = 0; s < 7; s++)
      #pragma unroll
      for (int rr = 0; rr < 8; rr++) acc[s][rr] = acc[s + 1][rr];

    // sort each kk[rr] descending across the warp (8 sorts vectorized)
    for (int kstep = 2; kstep <= 32; kstep <<= 1) {
      for (int j = kstep >> 1; j > 0; j >>= 1) {
        bool keepmax = (((lane & kstep) == 0) == ((lane & j) == 0));
        #pragma unroll
        for (int rr = 0; rr < 8; rr++) {
          unsigned long long o = __shfl_xor_sync(0xffffffffu, kk[rr], j);
          kk[rr] = keepmax ? kmax(kk[rr], o) : kmin(kk[rr], o);
        }
      }
    }
    // prune-merge tree: 8 sorted-32 -> top-32 of 256, sorted desc
    kk[0] = merge_top32(kk[0], kk[1], lane);
    kk[2] = merge_top32(kk[2], kk[3], lane);
    kk[4] = merge_top32(kk[4], kk[5], lane);
    kk[6] = merge_top32(kk[6], kk[7], lane);
    kk[0] = merge_top32(kk[0], kk[2], lane);
    kk[4] = merge_top32(kk[4], kk[6], lane);
    kk[0] = merge_top32(kk[0], kk[4], lane);

    unsigned u = (unsigned)(kk[0] >> 8);
    float v = __uint_as_float((u & 0x80000000u) ? (u ^ 0x80000000u) : ~u);
    int idx = ((int)(kk[0] & 0xffull)) ^ 0xff;
    size_t ob = (((size_t)t * NH + h) * 2 + p) * TK;
    g_sx[ob + lane] = v;
    g_ix[ob + lane] = idx;
  }
}

// ---- 5) cartesian combine top-32-of-1024 via 32-way sorted merge + softmax -
__global__ __launch_bounds__(256) void combine_kernel() {
  int w    = (blockIdx.x * 256 + threadIdx.x) >> 5;  // 0..16383
  int lane = threadIdx.x & 31;
  int t = w >> 3, h = w & 7;
  size_t bx = (((size_t)t * NH + h) * 2 + 0) * TK;
  float sx = g_sx[bx + lane];
  float sy = g_sx[bx + TK + lane];
  int  ixv = g_ix[bx + lane];
  int  iyv = g_ix[bx + TK + lane];

  int ptr = 0;
  float selS = 0.0f; int selVI = 0;
  for (int r = 0; r < TK; r++) {
    float syv  = __shfl_sync(0xffffffffu, sy, ptr & 31);
    float cand = (ptr < TK) ? (sx + syv) : NEG_INF;
    float bv = cand; int bl = lane;
    #pragma unroll
    for (int o = 16; o > 0; o >>= 1) {
      float ov = __shfl_xor_sync(0xffffffffu, bv, o);
      int   ol = __shfl_xor_sync(0xffffffffu, bl, o);
      if ((ov > bv) || (ov == bv && ol < bl)) { bv = ov; bl = ol; }
    }
    int jw  = __shfl_sync(0xffffffffu, ptr, bl);
    int ixw = __shfl_sync(0xffffffffu, ixv, bl);
    int iyw = __shfl_sync(0xffffffffu, iyv, jw & 31);
    if (lane == r) { selS = bv; selVI = ixw * NKEY + iyw; }
    if (lane == bl) ptr++;
  }
  float mx = __shfl_sync(0xffffffffu, selS, 0);
  float e = expf(selS - mx);
  float sum = e;
  #pragma unroll
  for (int o = 16; o > 0; o >>= 1) sum += __shfl_xor_sync(0xffffffffu, sum, o);
  size_t ob = ((size_t)t * NH + h) * TK;
  g_w [ob + lane] = e / sum;
  g_vi[ob + lane] = selVI;
}

// ---------------- 6) out[t] = sum_{h,k} w * values[vi]  (gather) ------------
__global__ __launch_bounds__(128) void gather_kernel(const float* __restrict__ values,
                                                     float* __restrict__ out) {
  __shared__ float sw[NH * TK];
  __shared__ int   sv[NH * TK];
  int t = blockIdx.x;
  int tid = threadIdx.x;
  size_t base = (size_t)t * (NH * TK);
  sw[tid]       = g_w [base + tid];
  sv[tid]       = g_vi[base + tid];
  sw[tid + 128] = g_w [base + tid + 128];
  sv[tid + 128] = g_vi[base + tid + 128];
  __syncthreads();

  const float4* V = (const float4*)values;
  float4 acc = make_float4(0.f, 0.f, 0.f, 0.f);
  #pragma unroll 4
  for (int r = 0; r < NH * TK; r++) {
    float wv = sw[r];
    float4 x = V[(size_t)sv[r] * 128 + tid];
    acc.x = fmaf(wv, x.x, acc.x);
    acc.y = fmaf(wv, x.y, acc.y);
    acc.z = fmaf(wv, x.z, acc.z);
    acc.w = fmaf(wv, x.w, acc.w);
  }
  ((float4*)out)[(size_t)t * 128 + tid] = acc;
}

// ---------------- launch --------------------------------------------------
extern "C" void kernel_launch(void* const* d_in, const int* in_sizes, int n_in,
                              void* d_out, int out_size) {
  const float* x      = (const float*)d_in[0];  // (2,1024,512)
  const float* Wq     = (const float*)d_in[1];  // (2048,512)
  const float* keys   = (const float*)d_in[2];  // (8,256,2,128)
  const float* values = (const float*)d_in[3];  // (65536,512)
  const float* gamma  = (const float*)d_in[4];  // (128)
  const float* beta   = (const float*)d_in[5];  // (128)
  float* out = (float*)d_out;                   // (2,1024,512)

  sgemm_q        <<<dim3(32, 16), 256>>>(x, Wq);
  ln_kernel      <<<4096, 256>>>(gamma, beta);
  dots_topk_kernel<<<dim3(32, 16), 256>>>(keys);
  combine_kernel <<<2048, 256>>>();
  gather_kernel  <<<2048, 128>>>(values, out);
}

// round 5
// speedup vs baseline: 1.1883x; 1.0024x over previous
#include <cuda_runtime.h>
#include <math.h>

#define NTOK 2048      // b*t
#define CDIM 512       // input dim
#define DQ   2048      // query dim = 2*H*DH
#define NH   8
#define NKEY 256
#define DH   128
#define TK   32
#define NEG_INF (-3.402823466e38f)

// ---------------- scratch (device globals; no allocations allowed) ----------
__device__ float g_q[NTOK * DQ];            // 16 MB  [t][p][h][d]
__device__ float g_sx[NTOK * 16 * TK];      // [t][h][p][k]  sorted desc
__device__ int   g_ix[NTOK * 16 * TK];
__device__ float g_w [NTOK * NH * TK];      // softmax weights
__device__ int   g_vi[NTOK * NH * TK];      // value row indices

// ---------------- 1) Q = X @ Wq^T  (M=2048,N=2048,K=512, fp32) --------------
__global__ __launch_bounds__(256) void sgemm_q(const float* __restrict__ X,
                                               const float* __restrict__ W) {
  __shared__ float As[16][128];   // transposed: As[k][m]
  __shared__ float Bs[16][64];    // transposed: Bs[k][n]
  const int m0 = blockIdx.y * 128;
  const int n0 = blockIdx.x * 64;
  const int tid = threadIdx.x;
  const int tm = tid >> 4;
  const int tn = tid & 15;
  const int ar = tid >> 2;
  const int ac = (tid & 3) * 4;

  float acc[8][4];
  #pragma unroll
  for (int i = 0; i < 8; i++) {
    #pragma unroll
    for (int j = 0; j < 4; j++) acc[i][j] = 0.0f;
  }

  for (int k0 = 0; k0 < CDIM; k0 += 16) {
    #pragma unroll
    for (int i = 0; i < 2; i++) {
      int r = ar + i * 64;
      float4 v = *(const float4*)(X + (size_t)(m0 + r) * CDIM + k0 + ac);
      As[ac + 0][r] = v.x; As[ac + 1][r] = v.y;
      As[ac + 2][r] = v.z; As[ac + 3][r] = v.w;
    }
    {
      float4 v = *(const float4*)(W + (size_t)(n0 + ar) * CDIM + k0 + ac);
      Bs[ac + 0][ar] = v.x; Bs[ac + 1][ar] = v.y;
      Bs[ac + 2][ar] = v.z; Bs[ac + 3][ar] = v.w;
    }
    __syncthreads();
    #pragma unroll
    for (int k = 0; k < 16; k++) {
      float4 b  = *(const float4*)&Bs[k][tn * 4];
      float4 a0 = *(const float4*)&As[k][tm * 8];
      float4 a1 = *(const float4*)&As[k][tm * 8 + 4];
      float av[8] = {a0.x, a0.y, a0.z, a0.w, a1.x, a1.y, a1.z, a1.w};
      float bv[4] = {b.x, b.y, b.z, b.w};
      #pragma unroll
      for (int i = 0; i < 8; i++) {
        #pragma unroll
        for (int j = 0; j < 4; j++) acc[i][j] = fmaf(av[i], bv[j], acc[i][j]);
      }
    }
    __syncthreads();
  }
  #pragma unroll
  for (int i = 0; i < 8; i++) {
    float4 v = make_float4(acc[i][0], acc[i][1], acc[i][2], acc[i][3]);
    *(float4*)(g_q + (size_t)(m0 + tm * 8 + i) * DQ + n0 + tn * 4) = v;
  }
}

// ---------------- 2) LayerNorm over each 128-group, in place ----------------
__global__ __launch_bounds__(256) void ln_kernel(const float* __restrict__ gamma,
                                                 const float* __restrict__ beta) {
  int g    = blockIdx.x * 8 + (threadIdx.x >> 5);
  int lane = threadIdx.x & 31;
  float* base = g_q + (size_t)g * DH;
  float v[4];
  #pragma unroll
  for (int j = 0; j < 4; j++) v[j] = base[lane + j * 32];
  float s = v[0] + v[1] + v[2] + v[3];
  #pragma unroll
  for (int o = 16; o > 0; o >>= 1) s += __shfl_xor_sync(0xffffffffu, s, o);
  float mean = s * (1.0f / 128.0f);
  float d[4];
  #pragma unroll
  for (int j = 0; j < 4; j++) d[j] = v[j] - mean;
  float sq = d[0]*d[0] + d[1]*d[1] + d[2]*d[2] + d[3]*d[3];
  #pragma unroll
  for (int o = 16; o > 0; o >>= 1) sq += __shfl_xor_sync(0xffffffffu, sq, o);
  float rs = rsqrtf(sq * (1.0f / 128.0f) + 1e-5f);
  #pragma unroll
  for (int j = 0; j < 4; j++) {
    int c = lane + j * 32;
    base[c] = d[j] * rs * gamma[c] + beta[c];
  }
}

// ---------------- bitonic helpers on u64 keys (desc, exact tie-break) -------
__device__ __forceinline__ unsigned long long kmax(unsigned long long a,
                                                   unsigned long long b) {
  return a > b ? a : b;
}
__device__ __forceinline__ unsigned long long kmin(unsigned long long a,
                                                   unsigned long long b) {
  return a < b ? a : b;
}
// merge two descending sorted-32 (one elem/lane) -> top-32 of union, desc
__device__ __forceinline__ unsigned long long merge_top32(
    unsigned long long a, unsigned long long b, int lane) {
  unsigned long long br = __shfl_sync(0xffffffffu, b, 31 - lane);
  unsigned long long m = kmax(a, br);   // bitonic, contains top-32
  #pragma unroll
  for (int j = 16; j > 0; j >>= 1) {
    unsigned long long o = __shfl_xor_sync(0xffffffffu, m, j);
    m = ((lane & j) == 0) ? kmax(m, o) : kmin(m, o);
  }
  return m;
}

// ------- 3+4) fused: dots (per hp, 64 tokens/block) + bitonic top-32 --------
// Warp w owns tokens t0+8w..t0+8w+7; lane owns key columns rr*32+lane.
__global__ __launch_bounds__(256) void dots_topk_kernel(const float* __restrict__ keys) {
  __shared__ float Qs[32][65];    // Qs[k][m] padded: conflict-free
  __shared__ float Ks[32][257];   // Ks[k][n] padded: conflict-free
  const int hp = blockIdx.y;              // 0..15
  const int h = hp >> 1, p = hp & 1;
  const int t0 = blockIdx.x * 64;
  const int tid = threadIdx.x;
  const int lane = tid & 31;
  const int w = tid >> 5;                 // warp 0..7

  const float* qbase = g_q + p * 1024 + h * 128;            // + t*DQ + d
  const float* kbase = keys + ((size_t)h * 512 + p) * 128;  // + n*256 + d

  float acc[8][8];                        // [token i][rr]
  #pragma unroll
  for (int i = 0; i < 8; i++)
    #pragma unroll
    for (int rr = 0; rr < 8; rr++) acc[i][rr] = 0.0f;

  for (int kt = 0; kt < DH; kt += 32) {
    #pragma unroll
    for (int i = 0; i < 2; i++) {
      int idx = tid + i * 256;            // 0..511
      int m = idx >> 3, c4 = (idx & 7) * 4;
      float4 v = *(const float4*)(qbase + (size_t)(t0 + m) * DQ + kt + c4);
      Qs[c4 + 0][m] = v.x; Qs[c4 + 1][m] = v.y;
      Qs[c4 + 2][m] = v.z; Qs[c4 + 3][m] = v.w;
    }
    #pragma unroll
    for (int i = 0; i < 8; i++) {
      int idx = tid + i * 256;            // 0..2047
      int n = idx >> 3, c4 = (idx & 7) * 4;
      float4 v = *(const float4*)(kbase + (size_t)n * 256 + kt + c4);
      Ks[c4 + 0][n] = v.x; Ks[c4 + 1][n] = v.y;
      Ks[c4 + 2][n] = v.z; Ks[c4 + 3][n] = v.w;
    }
    __syncthreads();
    #pragma unroll 1
    for (int k = 0; k < 32; k++) {
      float qv[8], kv[8];
      #pragma unroll
      for (int i = 0; i < 8; i++) qv[i] = Qs[k][w * 8 + i];     // broadcast
      #pragma unroll
      for (int rr = 0; rr < 8; rr++) kv[rr] = Ks[k][rr * 32 + lane];
      #pragma unroll
      for (int i = 0; i < 8; i++)
        #pragma unroll
        for (int rr = 0; rr < 8; rr++)
          acc[i][rr] = fmaf(qv[i], kv[rr], acc[i][rr]);
    }
    __syncthreads();
  }

  // ---- per-token top-32 via bitonic sort + prune-merge tree ----
  #pragma unroll 1
  for (int i = 0; i < 8; i++) {
    int t = t0 + w * 8 + i;
    unsigned long long kk[8];
    #pragma unroll
    for (int rr = 0; rr < 8; rr++) {
      unsigned u = __float_as_uint(acc[0][rr]);          // token data in slot 0
      u = (u & 0x80000000u) ? ~u : (u | 0x80000000u);    // monotonic map
      int idx = rr * 32 + lane;
      kk[rr] = ((unsigned long long)u << 8) | (unsigned)(idx ^ 0xff);
    }
    // rotate acc so next token's data moves into slot 0 (no dynamic reg index)
    #pragma unroll
    for (int s = 0; s < 7; s++)
      #pragma unroll
      for (int rr = 0; rr < 8; rr++) acc[s][rr] = acc[s + 1][rr];

    // sort each kk[rr] descending across the warp (8 sorts vectorized)
    for (int kstep = 2; kstep <= 32; kstep <<= 1) {
      for (int j = kstep >> 1; j > 0; j >>= 1) {
        bool keepmax = (((lane & kstep) == 0) == ((lane & j) == 0));
        #pragma unroll
        for (int rr = 0; rr < 8; rr++) {
          unsigned long long o = __shfl_xor_sync(0xffffffffu, kk[rr], j);
          kk[rr] = keepmax ? kmax(kk[rr], o) : kmin(kk[rr], o);
        }
      }
    }
    // prune-merge tree: 8 sorted-32 -> top-32 of 256, sorted desc
    kk[0] = merge_top32(kk[0], kk[1], lane);
    kk[2] = merge_top32(kk[2], kk[3], lane);
    kk[4] = merge_top32(kk[4], kk[5], lane);
    kk[6] = merge_top32(kk[6], kk[7], lane);
    kk[0] = merge_top32(kk[0], kk[2], lane);
    kk[4] = merge_top32(kk[4], kk[6], lane);
    kk[0] = merge_top32(kk[0], kk[4], lane);

    unsigned u = (unsigned)(kk[0] >> 8);
    float v = __uint_as_float((u & 0x80000000u) ? (u ^ 0x80000000u) : ~u);
    int idx = ((int)(kk[0] & 0xffull)) ^ 0xff;
    size_t ob = (((size_t)t * NH + h) * 2 + p) * TK;
    g_sx[ob + lane] = v;
    g_ix[ob + lane] = idx;
  }
}

// ---- 5) cartesian combine top-32-of-1024 via 32-way sorted merge + softmax -
__global__ __launch_bounds__(256) void combine_kernel() {
  int w    = (blockIdx.x * 256 + threadIdx.x) >> 5;  // 0..16383
  int lane = threadIdx.x & 31;
  int t = w >> 3, h = w & 7;
  size_t bx = (((size_t)t * NH + h) * 2 + 0) * TK;
  float sx = g_sx[bx + lane];
  float sy = g_sx[bx + TK + lane];
  int  ixv = g_ix[bx + lane];
  int  iyv = g_ix[bx + TK + lane];

  int ptr = 0;
  float selS = 0.0f; int selVI = 0;
  for (int r = 0; r < TK; r++) {
    float syv  = __shfl_sync(0xffffffffu, sy, ptr & 31);
    float cand = (ptr < TK) ? (sx + syv) : NEG_INF;
    float bv = cand; int bl = lane;
    #pragma unroll
    for (int o = 16; o > 0; o >>= 1) {
      float ov = __shfl_xor_sync(0xffffffffu, bv, o);
      int   ol = __shfl_xor_sync(0xffffffffu, bl, o);
      if ((ov > bv) || (ov == bv && ol < bl)) { bv = ov; bl = ol; }
    }
    int jw  = __shfl_sync(0xffffffffu, ptr, bl);
    int ixw = __shfl_sync(0xffffffffu, ixv, bl);
    int iyw = __shfl_sync(0xffffffffu, iyv, jw & 31);
    if (lane == r) { selS = bv; selVI = ixw * NKEY + iyw; }
    if (lane == bl) ptr++;
  }
  float mx = __shfl_sync(0xffffffffu, selS, 0);
  float e = expf(selS - mx);
  float sum = e;
  #pragma unroll
  for (int o = 16; o > 0; o >>= 1) sum += __shfl_xor_sync(0xffffffffu, sum, o);
  size_t ob = ((size_t)t * NH + h) * TK;
  g_w [ob + lane] = e / sum;
  g_vi[ob + lane] = selVI;
}

// ---------------- 6) out[t] = sum_{h,k} w * values[vi]  (gather) ------------
__global__ __launch_bounds__(128) void gather_kernel(const float* __restrict__ values,
                                                     float* __restrict__ out) {
  __shared__ float sw[NH * TK];
  __shared__ int   sv[NH * TK];
  int t = blockIdx.x;
  int tid = threadIdx.x;
  size_t base = (size_t)t * (NH * TK);
  sw[tid]       = g_w [base + tid];
  sv[tid]       = g_vi[base + tid];
  sw[tid + 128] = g_w [base + tid + 128];
  sv[tid + 128] = g_vi[base + tid + 128];
  __syncthreads();

  const float4* V = (const float4*)values;
  float4 acc = make_float4(0.f, 0.f, 0.f, 0.f);
  #pragma unroll 4
  for (int r = 0; r < NH * TK; r++) {
    float wv = sw[r];
    float4 x = V[(size_t)sv[r] * 128 + tid];
    acc.x = fmaf(wv, x.x, acc.x);
    acc.y = fmaf(wv, x.y, acc.y);
    acc.z = fmaf(wv, x.z, acc.z);
    acc.w = fmaf(wv, x.w, acc.w);
  }
  ((float4*)out)[(size_t)t * 128 + tid] = acc;
}

// ---------------- launch --------------------------------------------------
extern "C" void kernel_launch(void* const* d_in, const int* in_sizes, int n_in,
                              void* d_out, int out_size) {
  const float* x      = (const float*)d_in[0];  // (2,1024,512)
  const float* Wq     = (const float*)d_in[1];  // (2048,512)
  const float* keys   = (const float*)d_in[2];  // (8,256,2,128)
  const float* values = (const float*)d_in[3];  // (65536,512)
  const float* gamma  = (const float*)d_in[4];  // (128)
  const float* beta   = (const float*)d_in[5];  // (128)
  float* out = (float*)d_out;                   // (2,1024,512)

  sgemm_q        <<<dim3(32, 16), 256>>>(x, Wq);
  ln_kernel      <<<4096, 256>>>(gamma, beta);
  dots_topk_kernel<<<dim3(32, 16), 256>>>(keys);
  combine_kernel <<<2048, 256>>>();
  gather_kernel  <<<2048, 128>>>(values, out);
}

// round 6
// speedup vs baseline: 1.1885x; 1.0002x over previous
#include <cuda_runtime.h>
#include <math.h>

#define NTOK 2048      // b*t
#define CDIM 512       // input dim
#define DQ   2048      // query dim = 2*H*DH
#define NH   8
#define NKEY 256
#define DH   128
#define TK   32
#define NEG_INF (-3.402823466e38f)

// ---------------- scratch (device globals; no allocations allowed) ----------
__device__ float g_q[NTOK * DQ];            // 16 MB  [t][p][h][d]
__device__ float g_sx[NTOK * 16 * TK];      // [t][h][p][k]  sorted desc
__device__ int   g_ix[NTOK * 16 * TK];
__device__ float g_w [NTOK * NH * TK];      // softmax weights
__device__ int   g_vi[NTOK * NH * TK];      // value row indices

// ---------------- 1) Q = X @ Wq^T  (M=2048,N=2048,K=512, fp32) --------------
__global__ __launch_bounds__(256) void sgemm_q(const float* __restrict__ X,
                                               const float* __restrict__ W) {
  __shared__ float As[16][128];   // transposed: As[k][m]
  __shared__ float Bs[16][64];    // transposed: Bs[k][n]
  const int m0 = blockIdx.y * 128;
  const int n0 = blockIdx.x * 64;
  const int tid = threadIdx.x;
  const int tm = tid >> 4;
  const int tn = tid & 15;
  const int ar = tid >> 2;
  const int ac = (tid & 3) * 4;

  float acc[8][4];
  #pragma unroll
  for (int i = 0; i < 8; i++) {
    #pragma unroll
    for (int j = 0; j < 4; j++) acc[i][j] = 0.0f;
  }

  for (int k0 = 0; k0 < CDIM; k0 += 16) {
    #pragma unroll
    for (int i = 0; i < 2; i++) {
      int r = ar + i * 64;
      float4 v = *(const float4*)(X + (size_t)(m0 + r) * CDIM + k0 + ac);
      As[ac + 0][r] = v.x; As[ac + 1][r] = v.y;
      As[ac + 2][r] = v.z; As[ac + 3][r] = v.w;
    }
    {
      float4 v = *(const float4*)(W + (size_t)(n0 + ar) * CDIM + k0 + ac);
      Bs[ac + 0][ar] = v.x; Bs[ac + 1][ar] = v.y;
      Bs[ac + 2][ar] = v.z; Bs[ac + 3][ar] = v.w;
    }
    __syncthreads();
    #pragma unroll
    for (int k = 0; k < 16; k++) {
      float4 b  = *(const float4*)&Bs[k][tn * 4];
      float4 a0 = *(const float4*)&As[k][tm * 8];
      float4 a1 = *(const float4*)&As[k][tm * 8 + 4];
      float av[8] = {a0.x, a0.y, a0.z, a0.w, a1.x, a1.y, a1.z, a1.w};
      float bv[4] = {b.x, b.y, b.z, b.w};
      #pragma unroll
      for (int i = 0; i < 8; i++) {
        #pragma unroll
        for (int j = 0; j < 4; j++) acc[i][j] = fmaf(av[i], bv[j], acc[i][j]);
      }
    }
    __syncthreads();
  }
  #pragma unroll
  for (int i = 0; i < 8; i++) {
    float4 v = make_float4(acc[i][0], acc[i][1], acc[i][2], acc[i][3]);
    *(float4*)(g_q + (size_t)(m0 + tm * 8 + i) * DQ + n0 + tn * 4) = v;
  }
}

// ---------------- 2) LayerNorm over each 128-group, in place ----------------
__global__ __launch_bounds__(256) void ln_kernel(const float* __restrict__ gamma,
                                                 const float* __restrict__ beta) {
  int g    = blockIdx.x * 8 + (threadIdx.x >> 5);
  int lane = threadIdx.x & 31;
  float* base = g_q + (size_t)g * DH;
  float v[4];
  #pragma unroll
  for (int j = 0; j < 4; j++) v[j] = base[lane + j * 32];
  float s = v[0] + v[1] + v[2] + v[3];
  #pragma unroll
  for (int o = 16; o > 0; o >>= 1) s += __shfl_xor_sync(0xffffffffu, s, o);
  float mean = s * (1.0f / 128.0f);
  float d[4];
  #pragma unroll
  for (int j = 0; j < 4; j++) d[j] = v[j] - mean;
  float sq = d[0]*d[0] + d[1]*d[1] + d[2]*d[2] + d[3]*d[3];
  #pragma unroll
  for (int o = 16; o > 0; o >>= 1) sq += __shfl_xor_sync(0xffffffffu, sq, o);
  float rs = rsqrtf(sq * (1.0f / 128.0f) + 1e-5f);
  #pragma unroll
  for (int j = 0; j < 4; j++) {
    int c = lane + j * 32;
    base[c] = d[j] * rs * gamma[c] + beta[c];
  }
}

// ---------------- bitonic helpers on u64 keys (desc, exact tie-break) -------
__device__ __forceinline__ unsigned long long kmax(unsigned long long a,
                                                   unsigned long long b) {
  return a > b ? a : b;
}
__device__ __forceinline__ unsigned long long kmin(unsigned long long a,
                                                   unsigned long long b) {
  return a < b ? a : b;
}
// merge two descending sorted-32 (one elem/lane) -> top-32 of union, desc
__device__ __forceinline__ unsigned long long merge_top32(
    unsigned long long a, unsigned long long b, int lane) {
  unsigned long long br = __shfl_sync(0xffffffffu, b, 31 - lane);
  unsigned long long m = kmax(a, br);   // bitonic, contains top-32
  #pragma unroll
  for (int j = 16; j > 0; j >>= 1) {
    unsigned long long o = __shfl_xor_sync(0xffffffffu, m, j);
    m = ((lane & j) == 0) ? kmax(m, o) : kmin(m, o);
  }
  return m;
}

// ------- 3+4) fused: dots (per hp, 64 tokens/block) + bitonic top-32 --------
// Warp w owns tokens t0+8w..t0+8w+7; lane owns key columns rr*32+lane.
__global__ __launch_bounds__(256) void dots_topk_kernel(const float* __restrict__ keys) {
  __shared__ float Qs[32][65];    // Qs[k][m] padded: conflict-free
  __shared__ float Ks[32][257];   // Ks[k][n] padded: conflict-free
  const int hp = blockIdx.y;              // 0..15
  const int h = hp >> 1, p = hp & 1;
  const int t0 = blockIdx.x * 64;
  const int tid = threadIdx.x;
  const int lane = tid & 31;
  const int w = tid >> 5;                 // warp 0..7

  const float* qbase = g_q + p * 1024 + h * 128;            // + t*DQ + d
  const float* kbase = keys + ((size_t)h * 512 + p) * 128;  // + n*256 + d

  float acc[8][8];                        // [token i][rr]
  #pragma unroll
  for (int i = 0; i < 8; i++)
    #pragma unroll
    for (int rr = 0; rr < 8; rr++) acc[i][rr] = 0.0f;

  for (int kt = 0; kt < DH; kt += 32) {
    #pragma unroll
    for (int i = 0; i < 2; i++) {
      int idx = tid + i * 256;            // 0..511
      int m = idx >> 3, c4 = (idx & 7) * 4;
      float4 v = *(const float4*)(qbase + (size_t)(t0 + m) * DQ + kt + c4);
      Qs[c4 + 0][m] = v.x; Qs[c4 + 1][m] = v.y;
      Qs[c4 + 2][m] = v.z; Qs[c4 + 3][m] = v.w;
    }
    #pragma unroll
    for (int i = 0; i < 8; i++) {
      int idx = tid + i * 256;            // 0..2047
      int n = idx >> 3, c4 = (idx & 7) * 4;
      float4 v = *(const float4*)(kbase + (size_t)n * 256 + kt + c4);
      Ks[c4 + 0][n] = v.x; Ks[c4 + 1][n] = v.y;
      Ks[c4 + 2][n] = v.z; Ks[c4 + 3][n] = v.w;
    }
    __syncthreads();
    #pragma unroll 1
    for (int k = 0; k < 32; k++) {
      float qv[8], kv[8];
      #pragma unroll
      for (int i = 0; i < 8; i++) qv[i] = Qs[k][w * 8 + i];     // broadcast
      #pragma unroll
      for (int rr = 0; rr < 8; rr++) kv[rr] = Ks[k][rr * 32 + lane];
      #pragma unroll
      for (int i = 0; i < 8; i++)
        #pragma unroll
        for (int rr = 0; rr < 8; rr++)
          acc[i][rr] = fmaf(qv[i], kv[rr], acc[i][rr]);
    }
    __syncthreads();
  }

  // ---- per-token top-32 via bitonic sort + prune-merge tree ----
  #pragma unroll 1
  for (int i = 0; i < 8; i++) {
    int t = t0 + w * 8 + i;
    unsigned long long kk[8];
    #pragma unroll
    for (int rr = 0; rr < 8; rr++) {
      unsigned u = __float_as_uint(acc[0][rr]);          // token data in slot 0
      u = (u & 0x80000000u) ? ~u : (u | 0x80000000u);    // monotonic map
      int idx = rr * 32 + lane;
      kk[rr] = ((unsigned long long)u << 8) | (unsigned)(idx ^ 0xff);
    }
    // rotate acc so next token's data moves into slot 0 (no dynamic reg index)
    #pragma unroll
    for (int s = 0; s < 7; s++)
      #pragma unroll
      for (int rr = 0; rr < 8; rr++) acc[s][rr] = acc[s + 1][rr];

    // sort each kk[rr] descending across the warp (8 sorts vectorized)
    for (int kstep = 2; kstep <= 32; kstep <<= 1) {
      for (int j = kstep >> 1; j > 0; j >>= 1) {
        bool keepmax = (((lane & kstep) == 0) == ((lane & j) == 0));
        #pragma unroll
        for (int rr = 0; rr < 8; rr++) {
          unsigned long long o = __shfl_xor_sync(0xffffffffu, kk[rr], j);
          kk[rr] = keepmax ? kmax(kk[rr], o) : kmin(kk[rr], o);
        }
      }
    }
    // prune-merge tree: 8 sorted-32 -> top-32 of 256, sorted desc
    kk[0] = merge_top32(kk[0], kk[1], lane);
    kk[2] = merge_top32(kk[2], kk[3], lane);
    kk[4] = merge_top32(kk[4], kk[5], lane);
    kk[6] = merge_top32(kk[6], kk[7], lane);
    kk[0] = merge_top32(kk[0], kk[2], lane);
    kk[4] = merge_top32(kk[4], kk[6], lane);
    kk[0] = merge_top32(kk[0], kk[4], lane);

    unsigned u = (unsigned)(kk[0] >> 8);
    float v = __uint_as_float((u & 0x80000000u) ? (u ^ 0x80000000u) : ~u);
    int idx = ((int)(kk[0] & 0xffull)) ^ 0xff;
    size_t ob = (((size_t)t * NH + h) * 2 + p) * TK;
    g_sx[ob + lane] = v;
    g_ix[ob + lane] = idx;
  }
}

// ---- 5) cartesian combine top-32-of-1024 via 32-way sorted merge + softmax -
__global__ __launch_bounds__(256) void combine_kernel() {
  int w    = (blockIdx.x * 256 + threadIdx.x) >> 5;  // 0..16383
  int lane = threadIdx.x & 31;
  int t = w >> 3, h = w & 7;
  size_t bx = (((size_t)t * NH + h) * 2 + 0) * TK;
  float sx = g_sx[bx + lane];
  float sy = g_sx[bx + TK + lane];
  int  ixv = g_ix[bx + lane];
  int  iyv = g_ix[bx + TK + lane];

  int ptr = 0;
  float selS = 0.0f; int selVI = 0;
  for (int r = 0; r < TK; r++) {
    float syv  = __shfl_sync(0xffffffffu, sy, ptr & 31);
    float cand = (ptr < TK) ? (sx + syv) : NEG_INF;
    float bv = cand; int bl = lane;
    #pragma unroll
    for (int o = 16; o > 0; o >>= 1) {
      float ov = __shfl_xor_sync(0xffffffffu, bv, o);
      int   ol = __shfl_xor_sync(0xffffffffu, bl, o);
      if ((ov > bv) || (ov == bv && ol < bl)) { bv = ov; bl = ol; }
    }
    int jw  = __shfl_sync(0xffffffffu, ptr, bl);
    int ixw = __shfl_sync(0xffffffffu, ixv, bl);
    int iyw = __shfl_sync(0xffffffffu, iyv, jw & 31);
    if (lane == r) { selS = bv; selVI = ixw * NKEY + iyw; }
    if (lane == bl) ptr++;
  }
  float mx = __shfl_sync(0xffffffffu, selS, 0);
  float e = expf(selS - mx);
  float sum = e;
  #pragma unroll
  for (int o = 16; o > 0; o >>= 1) sum += __shfl_xor_sync(0xffffffffu, sum, o);
  size_t ob = ((size_t)t * NH + h) * TK;
  g_w [ob + lane] = e / sum;
  g_vi[ob + lane] = selVI;
}

// ---------------- 6) out[t] = sum_{h,k} w * values[vi]  (gather) ------------
__global__ __launch_bounds__(128) void gather_kernel(const float* __restrict__ values,
                                                     float* __restrict__ out) {
  __shared__ float sw[NH * TK];
  __shared__ int   sv[NH * TK];
  int t = blockIdx.x;
  int tid = threadIdx.x;
  size_t base = (size_t)t * (NH * TK);
  sw[tid]       = g_w [base + tid];
  sv[tid]       = g_vi[base + tid];
  sw[tid + 128] = g_w [base + tid + 128];
  sv[tid + 128] = g_vi[base + tid + 128];
  __syncthreads();

  const float4* V = (const float4*)values;
  float4 acc = make_float4(0.f, 0.f, 0.f, 0.f);
  #pragma unroll 4
  for (int r = 0; r < NH * TK; r++) {
    float wv = sw[r];
    float4 x = V[(size_t)sv[r] * 128 + tid];
    acc.x = fmaf(wv, x.x, acc.x);
    acc.y = fmaf(wv, x.y, acc.y);
    acc.z = fmaf(wv, x.z, acc.z);
    acc.w = fmaf(wv, x.w, acc.w);
  }
  ((float4*)out)[(size_t)t * 128 + tid] = acc;
}

// ---------------- launch --------------------------------------------------
extern "C" void kernel_launch(void* const* d_in, const int* in_sizes, int n_in,
                              void* d_out, int out_size) {
  const float* x      = (const float*)d_in[0];  // (2,1024,512)
  const float* Wq     = (const float*)d_in[1];  // (2048,512)
  const float* keys   = (const float*)d_in[2];  // (8,256,2,128)
  const float* values = (const float*)d_in[3];  // (65536,512)
  const float* gamma  = (const float*)d_in[4];  // (128)
  const float* beta   = (const float*)d_in[5];  // (128)
  float* out = (float*)d_out;                   // (2,1024,512)

  sgemm_q        <<<dim3(32, 16), 256>>>(x, Wq);
  ln_kernel      <<<4096, 256>>>(gamma, beta);
  dots_topk_kernel<<<dim3(32, 16), 256>>>(keys);
  combine_kernel <<<2048, 256>>>();
  gather_kernel  <<<2048, 128>>>(values, out);
}

// round 8
// speedup vs baseline: 1.2473x; 1.0495x over previous
#include <cuda_runtime.h>
#include <math.h>

#define NTOK 2048      // b*t
#define CDIM 512       // input dim
#define DQ   2048      // query dim = 2*H*DH
#define NH   8
#define NKEY 256
#define DH   128
#define TK   32
#define NEG_INF (-3.402823466e38f)

// ---------------- scratch (device globals; no allocations allowed) ----------
__device__ float g_q[NTOK * DQ];            // 16 MB  [t][p][h][d]
__device__ float g_sx[NTOK * 16 * TK];      // [t][h][p][k]  sorted desc
__device__ int   g_ix[NTOK * 16 * TK];
__device__ float g_w [NTOK * NH * TK];      // softmax weights
__device__ int   g_vi[NTOK * NH * TK];      // value row indices

// ---------------- packed f32x2 helpers (sm_100+ base ISA, no 'a' gate) ------
__device__ __forceinline__ void ffma2(unsigned long long& d,
                                      unsigned long long a,
                                      unsigned long long b) {
  asm("fma.rn.f32x2 %0, %1, %2, %0;" : "+l"(d) : "l"(a), "l"(b));
}
__device__ __forceinline__ unsigned long long dup2(float v) {
  unsigned long long r;
  unsigned u = __float_as_uint(v);
  asm("mov.b64 %0, {%1, %1};" : "=l"(r) : "r"(u));
  return r;
}
__device__ __forceinline__ float2 unpack2(unsigned long long v) {
  unsigned lo, hi;
  asm("mov.b64 {%0, %1}, %2;" : "=r"(lo), "=r"(hi) : "l"(v));
  return make_float2(__uint_as_float(lo), __uint_as_float(hi));
}

// ---------------- 1) Q = X @ Wq^T  (M=2048,N=2048,K=512, fp32x2) ------------
__global__ __launch_bounds__(256) void sgemm_q(const float* __restrict__ X,
                                               const float* __restrict__ W) {
  __shared__ float As[16][128];   // transposed: As[k][m]  (row 512B, 8B-aligned)
  __shared__ float Bs[16][64];    // transposed: Bs[k][n]
  const int m0 = blockIdx.y * 128;
  const int n0 = blockIdx.x * 64;
  const int tid = threadIdx.x;
  const int tm = tid >> 4;   // 0..15 -> 8 rows each
  const int tn = tid & 15;   // 0..15 -> 4 cols each
  const int ar = tid >> 2;   // 0..63
  const int ac = (tid & 3) * 4;

  // acc2[i2][j] = (acc[2*i2][j], acc[2*i2+1][j]) packed along M
  unsigned long long acc2[4][4];
  #pragma unroll
  for (int i = 0; i < 4; i++)
    #pragma unroll
    for (int j = 0; j < 4; j++) acc2[i][j] = 0ull;

  for (int k0 = 0; k0 < CDIM; k0 += 16) {
    #pragma unroll
    for (int i = 0; i < 2; i++) {
      int r = ar + i * 64;
      float4 v = *(const float4*)(X + (size_t)(m0 + r) * CDIM + k0 + ac);
      As[ac + 0][r] = v.x; As[ac + 1][r] = v.y;
      As[ac + 2][r] = v.z; As[ac + 3][r] = v.w;
    }
    {
      float4 v = *(const float4*)(W + (size_t)(n0 + ar) * CDIM + k0 + ac);
      Bs[ac + 0][ar] = v.x; Bs[ac + 1][ar] = v.y;
      Bs[ac + 2][ar] = v.z; Bs[ac + 3][ar] = v.w;
    }
    __syncthreads();
    #pragma unroll
    for (int k = 0; k < 16; k++) {
      const unsigned long long* pa =
          (const unsigned long long*)&As[k][tm * 8];   // 4 packed M-pairs
      unsigned long long a2[4] = {pa[0], pa[1], pa[2], pa[3]};
      float4 b = *(const float4*)&Bs[k][tn * 4];
      unsigned long long bd[4] = {dup2(b.x), dup2(b.y), dup2(b.z), dup2(b.w)};
      #pragma unroll
      for (int i = 0; i < 4; i++)
        #pragma unroll
        for (int j = 0; j < 4; j++) ffma2(acc2[i][j], a2[i], bd[j]);
    }
    __syncthreads();
  }
  #pragma unroll
  for (int i2 = 0; i2 < 4; i2++) {
    float2 c0 = unpack2(acc2[i2][0]);
    float2 c1 = unpack2(acc2[i2][1]);
    float2 c2 = unpack2(acc2[i2][2]);
    float2 c3 = unpack2(acc2[i2][3]);
    *(float4*)(g_q + (size_t)(m0 + tm * 8 + 2 * i2) * DQ + n0 + tn * 4) =
        make_float4(c0.x, c1.x, c2.x, c3.x);
    *(float4*)(g_q + (size_t)(m0 + tm * 8 + 2 * i2 + 1) * DQ + n0 + tn * 4) =
        make_float4(c0.y, c1.y, c2.y, c3.y);
  }
}

// ---------------- 2) LayerNorm over each 128-group, in place ----------------
__global__ __launch_bounds__(256) void ln_kernel(const float* __restrict__ gamma,
                                                 const float* __restrict__ beta) {
  int g    = blockIdx.x * 8 + (threadIdx.x >> 5);
  int lane = threadIdx.x & 31;
  float* base = g_q + (size_t)g * DH;
  float v[4];
  #pragma unroll
  for (int j = 0; j < 4; j++) v[j] = base[lane + j * 32];
  float s = v[0] + v[1] + v[2] + v[3];
  #pragma unroll
  for (int o = 16; o > 0; o >>= 1) s += __shfl_xor_sync(0xffffffffu, s, o);
  float mean = s * (1.0f / 128.0f);
  float d[4];
  #pragma unroll
  for (int j = 0; j < 4; j++) d[j] = v[j] - mean;
  float sq = d[0]*d[0] + d[1]*d[1] + d[2]*d[2] + d[3]*d[3];
  #pragma unroll
  for (int o = 16; o > 0; o >>= 1) sq += __shfl_xor_sync(0xffffffffu, sq, o);
  float rs = rsqrtf(sq * (1.0f / 128.0f) + 1e-5f);
  #pragma unroll
  for (int j = 0; j < 4; j++) {
    int c = lane + j * 32;
    base[c] = d[j] * rs * gamma[c] + beta[c];
  }
}

// ---------------- bitonic helpers on u64 keys (desc, exact tie-break) -------
__device__ __forceinline__ unsigned long long kmax(unsigned long long a,
                                                   unsigned long long b) {
  return a > b ? a : b;
}
__device__ __forceinline__ unsigned long long kmin(unsigned long long a,
                                                   unsigned long long b) {
  return a < b ? a : b;
}
// merge two descending sorted-32 (one elem/lane) -> top-32 of union, desc
__device__ __forceinline__ unsigned long long merge_top32(
    unsigned long long a, unsigned long long b, int lane) {
  unsigned long long br = __shfl_sync(0xffffffffu, b, 31 - lane);
  unsigned long long m = kmax(a, br);
  #pragma unroll
  for (int j = 16; j > 0; j >>= 1) {
    unsigned long long o = __shfl_xor_sync(0xffffffffu, m, j);
    m = ((lane & j) == 0) ? kmax(m, o) : kmin(m, o);
  }
  return m;
}

// per-token top-32 of 256 values (8 per lane), exact lax.top_k semantics
__device__ __forceinline__ void topk_store(const float v[8], int t, int h,
                                           int p, int lane) {
  unsigned long long kk[8];
  #pragma unroll
  for (int rr = 0; rr < 8; rr++) {
    unsigned u = __float_as_uint(v[rr]);
    u = (u & 0x80000000u) ? ~u : (u | 0x80000000u);
    int idx = rr * 32 + lane;
    kk[rr] = ((unsigned long long)u << 8) | (unsigned)(idx ^ 0xff);
  }
  for (int kstep = 2; kstep <= 32; kstep <<= 1) {
    for (int j = kstep >> 1; j > 0; j >>= 1) {
      bool keepmax = (((lane & kstep) == 0) == ((lane & j) == 0));
      #pragma unroll
      for (int rr = 0; rr < 8; rr++) {
        unsigned long long o = __shfl_xor_sync(0xffffffffu, kk[rr], j);
        kk[rr] = keepmax ? kmax(kk[rr], o) : kmin(kk[rr], o);
      }
    }
  }
  kk[0] = merge_top32(kk[0], kk[1], lane);
  kk[2] = merge_top32(kk[2], kk[3], lane);
  kk[4] = merge_top32(kk[4], kk[5], lane);
  kk[6] = merge_top32(kk[6], kk[7], lane);
  kk[0] = merge_top32(kk[0], kk[2], lane);
  kk[4] = merge_top32(kk[4], kk[6], lane);
  kk[0] = merge_top32(kk[0], kk[4], lane);

  unsigned u = (unsigned)(kk[0] >> 8);
  float val = __uint_as_float((u & 0x80000000u) ? (u ^ 0x80000000u) : ~u);
  int idx = ((int)(kk[0] & 0xffull)) ^ 0xff;
  size_t ob = (((size_t)t * NH + h) * 2 + p) * TK;
  g_sx[ob + lane] = val;
  g_ix[ob + lane] = idx;
}

// ------- 3+4) fused: dots (per hp, 64 tokens/block) + bitonic top-32 --------
// Warp w owns tokens t0+8w..t0+8w+7; lane owns key columns rr*32+lane.
// FMA mainloop packed f32x2 along the token dimension.
__global__ __launch_bounds__(256) void dots_topk_kernel(const float* __restrict__ keys) {
  __shared__ float Qs[32][66];    // row 264B: 8B-aligned pair loads
  __shared__ float Ks[32][257];   // conflict-free scalar loads
  const int hp = blockIdx.y;
  const int h = hp >> 1, p = hp & 1;
  const int t0 = blockIdx.x * 64;
  const int tid = threadIdx.x;
  const int lane = tid & 31;
  const int w = tid >> 5;

  const float* qbase = g_q + p * 1024 + h * 128;
  const float* kbase = keys + ((size_t)h * 512 + p) * 128;

  // acc2[i2][rr] = (dot[token 2*i2][rr], dot[token 2*i2+1][rr])
  unsigned long long acc2[4][8];
  #pragma unroll
  for (int i = 0; i < 4; i++)
    #pragma unroll
    for (int rr = 0; rr < 8; rr++) acc2[i][rr] = 0ull;

  for (int kt = 0; kt < DH; kt += 32) {
    #pragma unroll
    for (int i = 0; i < 2; i++) {
      int idx = tid + i * 256;
      int m = idx >> 3, c4 = (idx & 7) * 4;
      float4 v = *(const float4*)(qbase + (size_t)(t0 + m) * DQ + kt + c4);
      Qs[c4 + 0][m] = v.x; Qs[c4 + 1][m] = v.y;
      Qs[c4 + 2][m] = v.z; Qs[c4 + 3][m] = v.w;
    }
    #pragma unroll
    for (int i = 0; i < 8; i++) {
      int idx = tid + i * 256;
      int n = idx >> 3, c4 = (idx & 7) * 4;
      float4 v = *(const float4*)(kbase + (size_t)n * 256 + kt + c4);
      Ks[c4 + 0][n] = v.x; Ks[c4 + 1][n] = v.y;
      Ks[c4 + 2][n] = v.z; Ks[c4 + 3][n] = v.w;
    }
    __syncthreads();
    #pragma unroll 1
    for (int k = 0; k < 32; k++) {
      const unsigned long long* pq =
          (const unsigned long long*)&Qs[k][w * 8];   // 4 token-pairs (bcast)
      unsigned long long q2[4] = {pq[0], pq[1], pq[2], pq[3]};
      unsigned long long kd[8];
      #pragma unroll
      for (int rr = 0; rr < 8; rr++) kd[rr] = dup2(Ks[k][rr * 32 + lane]);
      #pragma unroll
      for (int i = 0; i < 4; i++)
        #pragma unroll
        for (int rr = 0; rr < 8; rr++) ffma2(acc2[i][rr], q2[i], kd[rr]);
    }
    __syncthreads();
  }

  #pragma unroll 1
  for (int i2 = 0; i2 < 4; i2++) {
    float vlo[8], vhi[8];
    #pragma unroll
    for (int rr = 0; rr < 8; rr++) {
      float2 c = unpack2(acc2[0][rr]);
      vlo[rr] = c.x; vhi[rr] = c.y;
    }
    #pragma unroll
    for (int s = 0; s < 3; s++)
      #pragma unroll
      for (int rr = 0; rr < 8; rr++) acc2[s][rr] = acc2[s + 1][rr];

    topk_store(vlo, t0 + w * 8 + 2 * i2,     h, p, lane);
    topk_store(vhi, t0 + w * 8 + 2 * i2 + 1, h, p, lane);
  }
}

// ---- 5) staircase combine: top-32 of sx_i+sy_j from 119 candidates ---------
// (i+1)*(j+1) <= 32 is necessary for top-32 membership (sorted desc inputs;
// every dominating pair also has a strictly smaller flat index, so the bound
// is exact under lax.top_k tie-breaking). 119 pairs, padded to 128.
__device__ const unsigned short c_tbl[128] = {
  0,1,2,3,4,5,6,7,8,9,10,11,12,13,14,15,
  16,17,18,19,20,21,22,23,24,25,26,27,28,29,30,31,
  32,33,34,35,36,37,38,39,40,41,42,43,44,45,46,47,
  64,65,66,67,68,69,70,71,72,73,
  96,97,98,99,100,101,102,103,
  128,129,130,131,132,133,
  160,161,162,163,164,
  192,193,194,195,
  224,225,226,227,
  256,257,258,
  288,289,290,
  320,321, 352,353, 384,385, 416,417, 448,449, 480,481,
  512,544,576,608,640,672,704,736,768,800,832,864,896,928,960,992,
  0xFFFF,0xFFFF,0xFFFF,0xFFFF,0xFFFF,0xFFFF,0xFFFF,0xFFFF,0xFFFF
};

__global__ __launch_bounds__(256) void combine_kernel() {
  int w    = (blockIdx.x * 256 + threadIdx.x) >> 5;  // 0..16383
  int lane = threadIdx.x & 31;
  int t = w >> 3, h = w & 7;
  size_t bx = (((size_t)t * NH + h) * 2) * TK;
  float sx = g_sx[bx + lane];
  float sy = g_sx[bx + TK + lane];
  int  ixv = g_ix[bx + lane];
  int  iyv = g_ix[bx + TK + lane];

  unsigned long long kk[4];
  #pragma unroll
  for (int g = 0; g < 4; g++) {
    unsigned v = c_tbl[g * 32 + lane];
    int i = (v == 0xFFFF) ? 0 : (int)(v >> 5);
    int j = (v == 0xFFFF) ? 0 : (int)(v & 31);
    float s = __shfl_sync(0xffffffffu, sx, i) + __shfl_sync(0xffffffffu, sy, j);
    unsigned u = __float_as_uint(s);
    u = (u & 0x80000000u) ? ~u : (u | 0x80000000u);
    unsigned long long key =
        ((unsigned long long)u << 10) | (unsigned)((i * 32 + j) ^ 0x3ff);
    kk[g] = (v == 0xFFFF) ? 0ull : key;   // padding always loses
  }
  // sort each group of 32 descending (vectorized x4)
  for (int kstep = 2; kstep <= 32; kstep <<= 1) {
    for (int j2 = kstep >> 1; j2 > 0; j2 >>= 1) {
      bool keepmax = (((lane & kstep) == 0) == ((lane & j2) == 0));
      #pragma unroll
      for (int g = 0; g < 4; g++) {
        unsigned long long o = __shfl_xor_sync(0xffffffffu, kk[g], j2);
        kk[g] = keepmax ? kmax(kk[g], o) : kmin(kk[g], o);
      }
    }
  }
  kk[0] = merge_top32(kk[0], kk[1], lane);
  kk[2] = merge_top32(kk[2], kk[3], lane);
  kk[0] = merge_top32(kk[0], kk[2], lane);

  unsigned flat = ((unsigned)kk[0] & 0x3ffu) ^ 0x3ffu;
  int i = (int)(flat >> 5), j = (int)(flat & 31);
  unsigned u = (unsigned)(kk[0] >> 10);
  float selS = __uint_as_float((u & 0x80000000u) ? (u ^ 0x80000000u) : ~u);
  int ixw = __shfl_sync(0xffffffffu, ixv, i);
  int iyw = __shfl_sync(0xffffffffu, iyv, j);
  int selVI = ixw * NKEY + iyw;

  float mx = __shfl_sync(0xffffffffu, selS, 0);   // sorted desc -> lane0 max
  float e = expf(selS - mx);
  float sum = e;
  #pragma unroll
  for (int o = 16; o > 0; o >>= 1) sum += __shfl_xor_sync(0xffffffffu, sum, o);
  size_t ob = ((size_t)t * NH + h) * TK;
  g_w [ob + lane] = e / sum;
  g_vi[ob + lane] = selVI;
}

// ---------------- 6) out[t] = sum_{h,k} w * values[vi]  (gather) ------------
__global__ __launch_bounds__(128) void gather_kernel(const float* __restrict__ values,
                                                     float* __restrict__ out) {
  __shared__ float sw[NH * TK];
  __shared__ int   sv[NH * TK];
  int t = blockIdx.x;
  int tid = threadIdx.x;
  size_t base = (size_t)t * (NH * TK);
  sw[tid]       = g_w [base + tid];
  sv[tid]       = g_vi[base + tid];
  sw[tid + 128] = g_w [base + tid + 128];
  sv[tid + 128] = g_vi[base + tid + 128];
  __syncthreads();

  const float4* V = (const float4*)values;
  float4 acc = make_float4(0.f, 0.f, 0.f, 0.f);
  #pragma unroll 4
  for (int r = 0; r < NH * TK; r++) {
    float wv = sw[r];
    float4 x = V[(size_t)sv[r] * 128 + tid];
    acc.x = fmaf(wv, x.x, acc.x);
    acc.y = fmaf(wv, x.y, acc.y);
    acc.z = fmaf(wv, x.z, acc.z);
    acc.w = fmaf(wv, x.w, acc.w);
  }
  ((float4*)out)[(size_t)t * 128 + tid] = acc;
}

// ---------------- launch --------------------------------------------------
extern "C" void kernel_launch(void* const* d_in, const int* in_sizes, int n_in,
                              void* d_out, int out_size) {
  const float* x      = (const float*)d_in[0];  // (2,1024,512)
  const float* Wq     = (const float*)d_in[1];  // (2048,512)
  const float* keys   = (const float*)d_in[2];  // (8,256,2,128)
  const float* values = (const float*)d_in[3];  // (65536,512)
  const float* gamma  = (const float*)d_in[4];  // (128)
  const float* beta   = (const float*)d_in[5];  // (128)
  float* out = (float*)d_out;                   // (2,1024,512)

  sgemm_q         <<<dim3(32, 16), 256>>>(x, Wq);
  ln_kernel       <<<4096, 256>>>(gamma, beta);
  dots_topk_kernel<<<dim3(32, 16), 256>>>(keys);
  combine_kernel  <<<2048, 256>>>();
  gather_kernel   <<<2048, 128>>>(values, out);
}

// round 10
// speedup vs baseline: 1.2960x; 1.0391x over previous
#include <cuda_runtime.h>
#include <math.h>

#define NTOK 2048      // b*t
#define CDIM 512       // input dim
#define DQ   2048      // query dim = 2*H*DH
#define NH   8
#define NKEY 256
#define DH   128
#define TK   32

// ---------------- scratch (device globals; no allocations allowed) ----------
__device__ float g_q[NTOK * DQ];            // 16 MB [t][p][h][d]
__device__ float g_w [NTOK * NH * TK];      // softmax weights
__device__ int   g_vi[NTOK * NH * TK];      // value row indices

// ---------------- packed f32x2 helpers --------------------------------------
__device__ __forceinline__ void ffma2(unsigned long long& d,
                                      unsigned long long a,
                                      unsigned long long b) {
  asm("fma.rn.f32x2 %0, %1, %2, %0;" : "+l"(d) : "l"(a), "l"(b));
}
__device__ __forceinline__ unsigned long long dup2(float v) {
  unsigned long long r;
  unsigned u = __float_as_uint(v);
  asm("mov.b64 %0, {%1, %1};" : "=l"(r) : "r"(u));
  return r;
}
__device__ __forceinline__ float2 unpack2(unsigned long long v) {
  unsigned lo, hi;
  asm("mov.b64 {%0, %1}, %2;" : "=r"(lo), "=r"(hi) : "l"(v));
  return make_float2(__uint_as_float(lo), __uint_as_float(hi));
}

// ---------- 1+2) Q = X @ Wq^T (fp32 FFMA) with fused LayerNorm --------------
// CTA tile 128x128: N-tile is exactly one (p,h) LN group of 128 dims, so the
// CTA holds complete LN rows. Thread (tm,tn) owns an 8x8 sub-tile.
__global__ __launch_bounds__(256, 2) void sgemm_ln(const float* __restrict__ X,
                                                   const float* __restrict__ W,
                                                   const float* __restrict__ gamma,
                                                   const float* __restrict__ beta) {
  __shared__ float As[16][132];   // As[k][m], padded
  __shared__ float Bs[16][132];   // Bs[k][n], padded
  __shared__ float red[128][17];  // LN partial sums
  const int tid = threadIdx.x;
  const int tm = tid >> 4;        // 0..15 -> 8 rows
  const int tn = tid & 15;        // 0..15 -> 8 cols
  const int m0 = blockIdx.y * 128;
  const int n0 = blockIdx.x * 128;
  const int ar = tid >> 1;        // 0..127
  const int ac = (tid & 1) * 8;   // 0 or 8

  float acc[8][8];
  #pragma unroll
  for (int i = 0; i < 8; i++)
    #pragma unroll
    for (int j = 0; j < 8; j++) acc[i][j] = 0.0f;

  for (int k0 = 0; k0 < CDIM; k0 += 16) {
    {
      const float* xp = X + (size_t)(m0 + ar) * CDIM + k0 + ac;
      float4 v0 = *(const float4*)xp;
      float4 v1 = *(const float4*)(xp + 4);
      As[ac + 0][ar] = v0.x; As[ac + 1][ar] = v0.y;
      As[ac + 2][ar] = v0.z; As[ac + 3][ar] = v0.w;
      As[ac + 4][ar] = v1.x; As[ac + 5][ar] = v1.y;
      As[ac + 6][ar] = v1.z; As[ac + 7][ar] = v1.w;
      const float* wp = W + (size_t)(n0 + ar) * CDIM + k0 + ac;
      float4 u0 = *(const float4*)wp;
      float4 u1 = *(const float4*)(wp + 4);
      Bs[ac + 0][ar] = u0.x; Bs[ac + 1][ar] = u0.y;
      Bs[ac + 2][ar] = u0.z; Bs[ac + 3][ar] = u0.w;
      Bs[ac + 4][ar] = u1.x; Bs[ac + 5][ar] = u1.y;
      Bs[ac + 6][ar] = u1.z; Bs[ac + 7][ar] = u1.w;
    }
    __syncthreads();
    #pragma unroll
    for (int k = 0; k < 16; k++) {
      float4 a0 = *(const float4*)&As[k][tm * 8];
      float4 a1 = *(const float4*)&As[k][tm * 8 + 4];
      float4 b0 = *(const float4*)&Bs[k][tn * 8];
      float4 b1 = *(const float4*)&Bs[k][tn * 8 + 4];
      float av[8] = {a0.x, a0.y, a0.z, a0.w, a1.x, a1.y, a1.z, a1.w};
      float bv[8] = {b0.x, b0.y, b0.z, b0.w, b1.x, b1.y, b1.z, b1.w};
      #pragma unroll
      for (int i = 0; i < 8; i++)
        #pragma unroll
        for (int j = 0; j < 8; j++) acc[i][j] = fmaf(av[i], bv[j], acc[i][j]);
    }
    __syncthreads();
  }

  // ---- fused LayerNorm over the 128-col group (whole CTA N range) ----
  float mean[8], rs[8];
  #pragma unroll
  for (int i = 0; i < 8; i++) {
    float s = 0.0f;
    #pragma unroll
    for (int j = 0; j < 8; j++) s += acc[i][j];
    red[tm * 8 + i][tn] = s;
  }
  __syncthreads();
  #pragma unroll
  for (int i = 0; i < 8; i++) {
    float s = 0.0f;
    #pragma unroll
    for (int c = 0; c < 16; c++) s += red[tm * 8 + i][c];
    mean[i] = s * (1.0f / 128.0f);
  }
  __syncthreads();
  #pragma unroll
  for (int i = 0; i < 8; i++) {
    float s = 0.0f;
    #pragma unroll
    for (int j = 0; j < 8; j++) {
      float d = acc[i][j] - mean[i];
      s += d * d;
    }
    red[tm * 8 + i][tn] = s;
  }
  __syncthreads();
  #pragma unroll
  for (int i = 0; i < 8; i++) {
    float s = 0.0f;
    #pragma unroll
    for (int c = 0; c < 16; c++) s += red[tm * 8 + i][c];
    rs[i] = rsqrtf(s * (1.0f / 128.0f) + 1e-5f);
  }

  float4 gm0 = __ldg((const float4*)(gamma + tn * 8));
  float4 gm1 = __ldg((const float4*)(gamma + tn * 8 + 4));
  float4 bt0 = __ldg((const float4*)(beta + tn * 8));
  float4 bt1 = __ldg((const float4*)(beta + tn * 8 + 4));
  float gv[8] = {gm0.x, gm0.y, gm0.z, gm0.w, gm1.x, gm1.y, gm1.z, gm1.w};
  float bv[8] = {bt0.x, bt0.y, bt0.z, bt0.w, bt1.x, bt1.y, bt1.z, bt1.w};

  #pragma unroll
  for (int i = 0; i < 8; i++) {
    float o[8];
    #pragma unroll
    for (int j = 0; j < 8; j++)
      o[j] = (acc[i][j] - mean[i]) * rs[i] * gv[j] + bv[j];
    float* op = g_q + (size_t)(m0 + tm * 8 + i) * DQ + n0 + tn * 8;
    *(float4*)op       = make_float4(o[0], o[1], o[2], o[3]);
    *(float4*)(op + 4) = make_float4(o[4], o[5], o[6], o[7]);
  }
}

// ---------------- bitonic helpers on u64 keys (desc, exact tie-break) -------
__device__ __forceinline__ unsigned long long kmax(unsigned long long a,
                                                   unsigned long long b) {
  return a > b ? a : b;
}
__device__ __forceinline__ unsigned long long kmin(unsigned long long a,
                                                   unsigned long long b) {
  return a < b ? a : b;
}
__device__ __forceinline__ unsigned long long merge_top32(
    unsigned long long a, unsigned long long b, int lane) {
  unsigned long long br = __shfl_sync(0xffffffffu, b, 31 - lane);
  unsigned long long m = kmax(a, br);
  #pragma unroll
  for (int j = 16; j > 0; j >>= 1) {
    unsigned long long o = __shfl_xor_sync(0xffffffffu, m, j);
    m = ((lane & j) == 0) ? kmax(m, o) : kmin(m, o);
  }
  return m;
}
__device__ __forceinline__ float key_val(unsigned long long k) {
  unsigned u = (unsigned)(k >> 8);
  return __uint_as_float((u & 0x80000000u) ? (u ^ 0x80000000u) : ~u);
}
__device__ __forceinline__ int key_idx(unsigned long long k) {
  return ((int)(k & 0xffull)) ^ 0xff;
}

// per-token top-32 of 256 values (8 per lane) -> sorted u64 key per lane
__device__ __forceinline__ unsigned long long topk_warp(const float v[8],
                                                        int lane) {
  unsigned long long kk[8];
  #pragma unroll
  for (int rr = 0; rr < 8; rr++) {
    unsigned u = __float_as_uint(v[rr]);
    u = (u & 0x80000000u) ? ~u : (u | 0x80000000u);
    int idx = rr * 32 + lane;
    kk[rr] = ((unsigned long long)u << 8) | (unsigned)(idx ^ 0xff);
  }
  for (int kstep = 2; kstep <= 32; kstep <<= 1) {
    for (int j = kstep >> 1; j > 0; j >>= 1) {
      bool keepmax = (((lane & kstep) == 0) == ((lane & j) == 0));
      #pragma unroll
      for (int rr = 0; rr < 8; rr++) {
        unsigned long long o = __shfl_xor_sync(0xffffffffu, kk[rr], j);
        kk[rr] = keepmax ? kmax(kk[rr], o) : kmin(kk[rr], o);
      }
    }
  }
  kk[0] = merge_top32(kk[0], kk[1], lane);
  kk[2] = merge_top32(kk[2], kk[3], lane);
  kk[4] = merge_top32(kk[4], kk[5], lane);
  kk[6] = merge_top32(kk[6], kk[7], lane);
  kk[0] = merge_top32(kk[0], kk[2], lane);
  kk[4] = merge_top32(kk[4], kk[6], lane);
  return merge_top32(kk[0], kk[4], lane);
}

// ---- staircase candidate table: (i+1)*(j+1) <= 32, 119 pairs padded to 128 -
__device__ const unsigned short c_tbl[128] = {
  0,1,2,3,4,5,6,7,8,9,10,11,12,13,14,15,
  16,17,18,19,20,21,22,23,24,25,26,27,28,29,30,31,
  32,33,34,35,36,37,38,39,40,41,42,43,44,45,46,47,
  64,65,66,67,68,69,70,71,72,73,
  96,97,98,99,100,101,102,103,
  128,129,130,131,132,133,
  160,161,162,163,164,
  192,193,194,195,
  224,225,226,227,
  256,257,258,
  288,289,290,
  320,321, 352,353, 384,385, 416,417, 448,449, 480,481,
  512,544,576,608,640,672,704,736,768,800,832,864,896,928,960,992,
  0xFFFF,0xFFFF,0xFFFF,0xFFFF,0xFFFF,0xFFFF,0xFFFF,0xFFFF,0xFFFF
};

// ------- 3+4+5) fused: dots (both p) + top-32 + staircase combine + softmax -
// Block: 64 tokens x one head. Warp w owns tokens t0+8w..+7; lane owns key
// columns rr*32+lane. p=0 and p=1 run sequentially reusing smem; both sorted
// top-32 lists then live in registers for the in-warp combine.
__global__ __launch_bounds__(256) void dtc_kernel(const float* __restrict__ keys) {
  __shared__ float Qs[32][66];
  __shared__ float Ks[32][257];
  const int h = blockIdx.y;               // 0..7
  const int t0 = blockIdx.x * 64;
  const int tid = threadIdx.x;
  const int lane = tid & 31;
  const int w = tid >> 5;

  unsigned long long res[2][8];

  #pragma unroll
  for (int p = 0; p < 2; p++) {
    const float* qbase = g_q + p * 1024 + h * 128;
    const float* kbase = keys + ((size_t)h * 512 + p) * 128;

    unsigned long long acc2[4][8];
    #pragma unroll
    for (int i = 0; i < 4; i++)
      #pragma unroll
      for (int rr = 0; rr < 8; rr++) acc2[i][rr] = 0ull;

    for (int kt = 0; kt < DH; kt += 32) {
      #pragma unroll
      for (int i = 0; i < 2; i++) {
        int idx = tid + i * 256;
        int m = idx >> 3, c4 = (idx & 7) * 4;
        float4 v = *(const float4*)(qbase + (size_t)(t0 + m) * DQ + kt + c4);
        Qs[c4 + 0][m] = v.x; Qs[c4 + 1][m] = v.y;
        Qs[c4 + 2][m] = v.z; Qs[c4 + 3][m] = v.w;
      }
      #pragma unroll
      for (int i = 0; i < 8; i++) {
        int idx = tid + i * 256;
        int n = idx >> 3, c4 = (idx & 7) * 4;
        float4 v = *(const float4*)(kbase + (size_t)n * 256 + kt + c4);
        Ks[c4 + 0][n] = v.x; Ks[c4 + 1][n] = v.y;
        Ks[c4 + 2][n] = v.z; Ks[c4 + 3][n] = v.w;
      }
      __syncthreads();
      #pragma unroll 1
      for (int k = 0; k < 32; k++) {
        const unsigned long long* pq =
            (const unsigned long long*)&Qs[k][w * 8];
        unsigned long long q2[4] = {pq[0], pq[1], pq[2], pq[3]};
        unsigned long long kd[8];
        #pragma unroll
        for (int rr = 0; rr < 8; rr++) kd[rr] = dup2(Ks[k][rr * 32 + lane]);
        #pragma unroll
        for (int i = 0; i < 4; i++)
          #pragma unroll
          for (int rr = 0; rr < 8; rr++) ffma2(acc2[i][rr], q2[i], kd[rr]);
      }
      __syncthreads();
    }

    #pragma unroll 1
    for (int i2 = 0; i2 < 4; i2++) {
      float vlo[8], vhi[8];
      #pragma unroll
      for (int rr = 0; rr < 8; rr++) {
        float2 c = unpack2(acc2[0][rr]);
        vlo[rr] = c.x; vhi[rr] = c.y;
      }
      #pragma unroll
      for (int s = 0; s < 3; s++)
        #pragma unroll
        for (int rr = 0; rr < 8; rr++) acc2[s][rr] = acc2[s + 1][rr];

      res[p][2 * i2]     = topk_warp(vlo, lane);
      res[p][2 * i2 + 1] = topk_warp(vhi, lane);
    }
  }

  // ---- staircase combine + softmax per token (all in registers) ----
  #pragma unroll 1
  for (int i = 0; i < 8; i++) {
    int t = t0 + w * 8 + i;
    float sx = key_val(res[0][i]);
    float sy = key_val(res[1][i]);
    int  ixv = key_idx(res[0][i]);
    int  iyv = key_idx(res[1][i]);

    unsigned long long kc[4];
    #pragma unroll
    for (int g = 0; g < 4; g++) {
      unsigned v = c_tbl[g * 32 + lane];
      int ci = (v == 0xFFFF) ? 0 : (int)(v >> 5);
      int cj = (v == 0xFFFF) ? 0 : (int)(v & 31);
      float s = __shfl_sync(0xffffffffu, sx, ci) +
                __shfl_sync(0xffffffffu, sy, cj);
      unsigned u = __float_as_uint(s);
      u = (u & 0x80000000u) ? ~u : (u | 0x80000000u);
      unsigned long long key =
          ((unsigned long long)u << 10) | (unsigned)((ci * 32 + cj) ^ 0x3ff);
      kc[g] = (v == 0xFFFF) ? 0ull : key;
    }
    for (int kstep = 2; kstep <= 32; kstep <<= 1) {
      for (int j2 = kstep >> 1; j2 > 0; j2 >>= 1) {
        bool keepmax = (((lane & kstep) == 0) == ((lane & j2) == 0));
        #pragma unroll
        for (int g = 0; g < 4; g++) {
          unsigned long long o = __shfl_xor_sync(0xffffffffu, kc[g], j2);
          kc[g] = keepmax ? kmax(kc[g], o) : kmin(kc[g], o);
        }
      }
    }
    kc[0] = merge_top32(kc[0], kc[1], lane);
    kc[2] = merge_top32(kc[2], kc[3], lane);
    kc[0] = merge_top32(kc[0], kc[2], lane);

    unsigned flat = ((unsigned)kc[0] & 0x3ffu) ^ 0x3ffu;
    int ci = (int)(flat >> 5), cj = (int)(flat & 31);
    unsigned u = (unsigned)(kc[0] >> 10);
    float selS = __uint_as_float((u & 0x80000000u) ? (u ^ 0x80000000u) : ~u);
    int ixw = __shfl_sync(0xffffffffu, ixv, ci);
    int iyw = __shfl_sync(0xffffffffu, iyv, cj);
    int selVI = ixw * NKEY + iyw;

    float mx = __shfl_sync(0xffffffffu, selS, 0);   // sorted desc
    float e = expf(selS - mx);
    float sum = e;
    #pragma unroll
    for (int o = 16; o > 0; o >>= 1) sum += __shfl_xor_sync(0xffffffffu, sum, o);
    size_t ob = ((size_t)t * NH + h) * TK;
    g_w [ob + lane] = e / sum;
    g_vi[ob + lane] = selVI;
  }
}

// ---------------- 6) out[t] = sum_{h,k} w * values[vi]  (gather) ------------
__global__ __launch_bounds__(128) void gather_kernel(const float* __restrict__ values,
                                                     float* __restrict__ out) {
  __shared__ float sw[NH * TK];
  __shared__ int   sv[NH * TK];
  int t = blockIdx.x;
  int tid = threadIdx.x;
  size_t base = (size_t)t * (NH * TK);
  sw[tid]       = g_w [base + tid];
  sv[tid]       = g_vi[base + tid];
  sw[tid + 128] = g_w [base + tid + 128];
  sv[tid + 128] = g_vi[base + tid + 128];
  __syncthreads();

  const float4* V = (const float4*)values;
  float4 acc = make_float4(0.f, 0.f, 0.f, 0.f);
  #pragma unroll 4
  for (int r = 0; r < NH * TK; r++) {
    float wv = sw[r];
    float4 x = V[(size_t)sv[r] * 128 + tid];
    acc.x = fmaf(wv, x.x, acc.x);
    acc.y = fmaf(wv, x.y, acc.y);
    acc.z = fmaf(wv, x.z, acc.z);
    acc.w = fmaf(wv, x.w, acc.w);
  }
  ((float4*)out)[(size_t)t * 128 + tid] = acc;
}

// ---------------- launch --------------------------------------------------
extern "C" void kernel_launch(void* const* d_in, const int* in_sizes, int n_in,
                              void* d_out, int out_size) {
  const float* x      = (const float*)d_in[0];  // (2,1024,512)
  const float* Wq     = (const float*)d_in[1];  // (2048,512)
  const float* keys   = (const float*)d_in[2];  // (8,256,2,128)
  const float* values = (const float*)d_in[3];  // (65536,512)
  const float* gamma  = (const float*)d_in[4];  // (128)
  const float* beta   = (const float*)d_in[5];  // (128)
  float* out = (float*)d_out;                   // (2,1024,512)

  sgemm_ln     <<<dim3(16, 16), 256>>>(x, Wq, gamma, beta);
  dtc_kernel   <<<dim3(32, 8), 256>>>(keys);
  gather_kernel<<<2048, 128>>>(values, out);
}